// round 6
// baseline (speedup 1.0000x reference)
#include <cuda_runtime.h>
#include <math.h>

#define NBLK 128
#define NTHR 1024
#define MAXN 4096
#define MAXS 27
#define MAXC (MAXS * MAXN)
#define NGRID 10
#define NCELL (NGRID * NGRID * NGRID)
#define MAXPA 192

__device__ float4 g_bimg4[MAXC];
__device__ int    g_cfill[NCELL];   // zero at load; re-zeroed post-B0 every launch
__device__ int    g_cnt[MAXN];
__device__ unsigned g_barcnt, g_bargen;

#define MUL(a, b) __fmul_rn((a), (b))
#define ADD(a, b) __fadd_rn((a), (b))
#define SUB(a, b) __fsub_rn((a), (b))
#define DIV(a, b) __fdiv_rn((a), (b))

__device__ __forceinline__ unsigned fkey(float f) {
    unsigned u = __float_as_uint(f);
    return (u & 0x80000000u) ? ~u : (u | 0x80000000u);
}
__device__ __forceinline__ float fdec(unsigned k) {
    unsigned u = (k & 0x80000000u) ? (k & 0x7fffffffu) : ~k;
    return __uint_as_float(u);
}

// grid barrier: all NBLK blocks co-resident (128 blocks, 1/SM)
__device__ __forceinline__ void gbar(unsigned target) {
    __syncthreads();
    if (threadIdx.x == 0) {
        __threadfence();
        unsigned a = atomicAdd(&g_barcnt, 1u);
        if (a == NBLK - 1u) {
            g_barcnt = 0u;
            __threadfence();
            atomicExch(&g_bargen, target);
        } else {
            while ((int)(*(volatile unsigned*)&g_bargen - target) < 0) { }
            __threadfence();
        }
    }
    __syncthreads();
}

// exclusive scan over 1024 threads; 3 syncthreads
__device__ __forceinline__ int scanExcl1024(int v, int* stmp, int lane, int wid) {
    __syncthreads();
    int x = v;
#pragma unroll
    for (int o = 1; o < 32; o <<= 1) {
        int y = __shfl_up_sync(0xffffffffu, x, o);
        if (lane >= o) x += y;
    }
    if (lane == 31) stmp[wid] = x;
    __syncthreads();
    if (wid == 0) {
        int s = stmp[lane];
#pragma unroll
        for (int o = 1; o < 32; o <<= 1) {
            int y = __shfl_up_sync(0xffffffffu, s, o);
            if (lane >= o) s += y;
        }
        stmp[lane] = s;
    }
    __syncthreads();
    int base = wid ? stmp[wid - 1] : 0;
    return base + x - v;
}

extern __shared__ char dynsmem[];

__global__ __launch_bounds__(NTHR, 1)
void k_all(const float* __restrict__ cell, const int* __restrict__ period,
           const float* __restrict__ coords, const float* __restrict__ mass,
           int N, int P, float* __restrict__ out) {
    __shared__ float sinv[9], sfrac0[3], sshifts[MAXS * 3];
    __shared__ float scom[3], sminc[3], smaxc[3];
    __shared__ int   sS;
    __shared__ int   stmp[33];
    __shared__ unsigned skey[32];
    __shared__ unsigned sredmin[3], sredmax[3];
    __shared__ int   sWoff[32];

    // dynamic shared carve-up
    double* sd    = (double*)dynsmem;                 // 32768B COM tree (phase A)
    int*    s_hist= (int*)dynsmem;                    // alias (after COM)
    int*    sj    = (int*)dynsmem;                    // alias (search/write)
    float*  s_wx  = (float*)(dynsmem + 32768);
    float*  s_wy  = s_wx + N;
    float*  s_wz  = s_wy + N;
    int*    scoff = (int*)(dynsmem + 32768 + 3 * 4 * N);

    const int t = threadIdx.x, b = blockIdx.x;
    const int lane = t & 31, wid = t >> 5;
    const int gt = b * NTHR + t;
    unsigned gen = *(volatile unsigned*)&g_bargen;

    // ================= PHASE A: all block-local =================
    if (t == 0) {
        float m00 = cell[0], m01 = cell[1], m02 = cell[2];
        float m10 = cell[3], m11 = cell[4], m12 = cell[5];
        float m20 = cell[6], m21 = cell[7], m22 = cell[8];
        float c00 = SUB(MUL(m11, m22), MUL(m12, m21));
        float c10 = SUB(MUL(m12, m20), MUL(m10, m22));
        float c20 = SUB(MUL(m10, m21), MUL(m11, m20));
        float det = ADD(ADD(MUL(m00, c00), MUL(m01, c10)), MUL(m02, c20));
        sinv[0] = DIV(c00, det);
        sinv[1] = DIV(SUB(MUL(m02, m21), MUL(m01, m22)), det);
        sinv[2] = DIV(SUB(MUL(m01, m12), MUL(m02, m11)), det);
        sinv[3] = DIV(c10, det);
        sinv[4] = DIV(SUB(MUL(m00, m22), MUL(m02, m20)), det);
        sinv[5] = DIV(SUB(MUL(m02, m10), MUL(m00, m12)), det);
        sinv[6] = DIV(c20, det);
        sinv[7] = DIV(SUB(MUL(m01, m20), MUL(m00, m21)), det);
        sinv[8] = DIV(SUB(MUL(m00, m11), MUL(m01, m10)), det);
        float x0 = coords[0], y0 = coords[1], z0 = coords[2];
        for (int d = 0; d < 3; d++)
            sfrac0[d] = ADD(ADD(MUL(x0, sinv[0 + d]), MUL(y0, sinv[3 + d])), MUL(z0, sinv[6 + d]));
        int nrep[3];
        for (int i = 0; i < 3; i++) {
            float r = DIV(5.0f, fabsf(cell[0 + i]));
            float r1 = DIV(5.0f, fabsf(cell[3 + i]));
            float r2 = DIV(5.0f, fabsf(cell[6 + i]));
            if (r1 < r) r = r1;
            if (r2 < r) r = r2;
            nrep[i] = (int)ceilf(r) * period[i];
        }
        int idx = 0;
        for (int a = -nrep[0]; a <= nrep[0]; a++)
            for (int bb = -nrep[1]; bb <= nrep[1]; bb++)
                for (int c = -nrep[2]; c <= nrep[2]; c++) {
                    if (idx < MAXS) {
                        float fa = (float)a, fb = (float)bb, fc = (float)c;
                        for (int d = 0; d < 3; d++)
                            sshifts[idx * 3 + d] =
                                ADD(ADD(MUL(fa, cell[0 + d]), MUL(fb, cell[3 + d])), MUL(fc, cell[6 + d]));
                    }
                    idx++;
                }
        sS = (idx > MAXS) ? MAXS : idx;
    }
    __syncthreads();
    const int S = sS;
    const int NS = S * N;
    const int CH = (NS + NBLK - 1) / NBLK;

    // wrap ALL atoms into shared (redundant per block; values identical everywhere)
    for (int i = t; i < N; i += NTHR) {
        float x = coords[i * 3 + 0], y = coords[i * 3 + 1], z = coords[i * 3 + 2];
        float f[3];
        for (int d = 0; d < 3; d++)
            f[d] = ADD(ADD(MUL(x, sinv[0 + d]), MUL(y, sinv[3 + d])), MUL(z, sinv[6 + d]));
        for (int d = 0; d < 3; d++)
            f[d] = SUB(f[d], rintf(SUB(f[d], sfrac0[d])));
        s_wx[i] = ADD(ADD(MUL(f[0], cell[0]), MUL(f[1], cell[3])), MUL(f[2], cell[6]));
        s_wy[i] = ADD(ADD(MUL(f[0], cell[1]), MUL(f[1], cell[4])), MUL(f[2], cell[7]));
        s_wz[i] = ADD(ADD(MUL(f[0], cell[2]), MUL(f[1], cell[5])), MUL(f[2], cell[8]));
    }
    __syncthreads();

    // COM: bit-identical accumulation order to R1-R4
    {
        double s0 = 0.0, s1 = 0.0, s2 = 0.0, s3 = 0.0;
        for (int i = t; i < N; i += NTHR) {
            double m = (double)mass[i];
            s0 += m * (double)s_wx[i];
            s1 += m * (double)s_wy[i];
            s2 += m * (double)s_wz[i];
            s3 += m;
        }
        sd[t] = s0; sd[1024 + t] = s1; sd[2048 + t] = s2; sd[3072 + t] = s3;
        __syncthreads();
        for (int off = 512; off > 0; off >>= 1) {
            if (t < off) {
                sd[t] += sd[t + off];
                sd[1024 + t] += sd[1024 + t + off];
                sd[2048 + t] += sd[2048 + t + off];
                sd[3072 + t] += sd[3072 + t + off];
            }
            __syncthreads();
        }
        if (t == 0) {
            float sm = (float)sd[3072];
            scom[0] = DIV((float)sd[0], sm);
            scom[1] = DIV((float)sd[1024], sm);
            scom[2] = DIV((float)sd[2048], sm);
        }
        __syncthreads();
    }

    // min/max over centered coords (exact, order-free key reductions)
    {
        unsigned kmn[3] = {~0u, ~0u, ~0u}, kmx[3] = {0u, 0u, 0u};
        for (int i = t; i < N; i += NTHR) {
            unsigned k0 = fkey(SUB(s_wx[i], scom[0]));
            unsigned k1 = fkey(SUB(s_wy[i], scom[1]));
            unsigned k2 = fkey(SUB(s_wz[i], scom[2]));
            kmn[0] = min(kmn[0], k0); kmx[0] = max(kmx[0], k0);
            kmn[1] = min(kmn[1], k1); kmx[1] = max(kmx[1], k1);
            kmn[2] = min(kmn[2], k2); kmx[2] = max(kmx[2], k2);
        }
#pragma unroll
        for (int d = 0; d < 3; d++) {
            unsigned v = kmn[d];
#pragma unroll
            for (int o = 16; o; o >>= 1) v = min(v, __shfl_xor_sync(0xffffffffu, v, o));
            if (lane == 0) skey[wid] = v;
            __syncthreads();
            if (wid == 0) {
                unsigned s = skey[lane];
#pragma unroll
                for (int o = 16; o; o >>= 1) s = min(s, __shfl_xor_sync(0xffffffffu, s, o));
                if (lane == 0) sredmin[d] = s;
            }
            __syncthreads();
            v = kmx[d];
#pragma unroll
            for (int o = 16; o; o >>= 1) v = max(v, __shfl_xor_sync(0xffffffffu, v, o));
            if (lane == 0) skey[wid] = v;
            __syncthreads();
            if (wid == 0) {
                unsigned s = skey[lane];
#pragma unroll
                for (int o = 16; o; o >>= 1) s = max(s, __shfl_xor_sync(0xffffffffu, s, o));
                if (lane == 0) sredmax[d] = s;
            }
            __syncthreads();
        }
        if (t < 3) {
            float mn = SUB(SUB(fdec(sredmin[t]), 5.0f), 1e-6f);
            sminc[t] = mn;
            smaxc[t] = ADD(SUB(fdec(sredmax[t]), mn), 5.0f);
        }
        __syncthreads();
    }

    // transform in place: s_w* := c2 (same fp expression as R4)
    for (int i = t; i < N; i += NTHR) {
        s_wx[i] = SUB(SUB(s_wx[i], scom[0]), sminc[0]);
        s_wy[i] = SUB(SUB(s_wy[i], scom[1]), sminc[1]);
        s_wz[i] = SUB(SUB(s_wz[i], scom[2]), sminc[2]);
    }
    __syncthreads();

    // shared histogram over ALL images (redundant per block, no int division)
    const float maxc0 = smaxc[0], maxc1 = smaxc[1], maxc2 = smaxc[2];
    for (int i = t; i < NCELL; i += NTHR) s_hist[i] = 0;
    __syncthreads();
    for (int s = 0; s < S; s++) {
        float sh0 = sshifts[s * 3 + 0], sh1 = sshifts[s * 3 + 1], sh2 = sshifts[s * 3 + 2];
        for (int a = t; a < N; a += NTHR) {
            float v0 = ADD(s_wx[a], sh0);
            float v1 = ADD(s_wy[a], sh1);
            float v2 = ADD(s_wz[a], sh2);
            if ((v0 > 0.f) && (v0 < maxc0) && (v1 > 0.f) && (v1 < maxc1) &&
                (v2 > 0.f) && (v2 < maxc2)) {
                int cx = min(max((int)floorf(DIV(v0, 5.0f)), 0), NGRID - 1);
                int cy = min(max((int)floorf(DIV(v1, 5.0f)), 0), NGRID - 1);
                int cz = min(max((int)floorf(DIV(v2, 5.0f)), 0), NGRID - 1);
                atomicAdd(&s_hist[cx + NGRID * (cy + NGRID * cz)], 1);
            }
        }
    }
    __syncthreads();   // <-- R5 BUG FIX: histogram must be complete before it is read

    // block-local scan -> scoff (valid in every block; identical everywhere)
    {
        int cv = (t < NCELL) ? s_hist[t] : 0;
        int ce = scanExcl1024(cv, stmp, lane, wid);
        if (t <= NCELL + 4) scoff[t] = ce;   // t >= NCELL carry the total
        __syncthreads();
    }

    // scatter own slice of images into global buckets
    {
        int end = min((b + 1) * CH, NS);
        for (int idx = b * CH + t; idx < end; idx += NTHR) {
            int s = idx / N;
            int a = idx - s * N;
            float v0 = ADD(s_wx[a], sshifts[s * 3 + 0]);
            float v1 = ADD(s_wy[a], sshifts[s * 3 + 1]);
            float v2 = ADD(s_wz[a], sshifts[s * 3 + 2]);
            if ((v0 > 0.f) && (v0 < maxc0) && (v1 > 0.f) && (v1 < maxc1) &&
                (v2 > 0.f) && (v2 < maxc2)) {
                int cx = min(max((int)floorf(DIV(v0, 5.0f)), 0), NGRID - 1);
                int cy = min(max((int)floorf(DIV(v1, 5.0f)), 0), NGRID - 1);
                int cz = min(max((int)floorf(DIV(v2, 5.0f)), 0), NGRID - 1);
                int c = cx + NGRID * (cy + NGRID * cz);
                int pos = scoff[c] + atomicAdd(&g_cfill[c], 1);
                g_bimg4[pos] = make_float4(v0, v1, v2, __int_as_float(idx));
            }
        }
    }
    gbar(++gen);  // B0: buckets complete

    // re-zero g_cfill for next replay (determinism); not read again this launch
    for (int i = gt; i < NCELL; i += NBLK * NTHR) g_cfill[i] = 0;

    // ================= PHASE B: per-atom search + in-warp rank sort =================
    {
        int w = wid * NBLK + b;
        int* sjw = sj + wid * MAXPA;
        int cur = 0;
        if (w < N) {
            float cx = s_wx[w], cy = s_wy[w], cz = s_wz[w];
            int ax = (int)floorf(DIV(cx, 5.0f));
            int ay = (int)floorf(DIV(cy, 5.0f));
            int az = (int)floorf(DIV(cz, 5.0f));
#pragma unroll
            for (int dz = -1; dz <= 1; dz++)
#pragma unroll
                for (int dy = -1; dy <= 1; dy++) {
                    int row = (ax - 1) + NGRID * ((ay + dy) + NGRID * (az + dz));
                    int s0 = scoff[row];
                    int e0 = scoff[row + 3];  // 3 consecutive x-cells merged
                    for (int k0 = s0; k0 < e0; k0 += 32) {
                        int k = k0 + lane;
                        bool hit = false;
                        int jidx = 0;
                        if (k < e0) {
                            float4 p = g_bimg4[k];
                            float ddx = SUB(cx, p.x);
                            float ddy = SUB(cy, p.y);
                            float ddz = SUB(cz, p.z);
                            float r2 = ADD(ADD(MUL(ddx, ddx), MUL(ddy, ddy)), MUL(ddz, ddz));
                            float dd = __fsqrt_rn(r2);
                            hit = (dd < 5.0f) && (dd > 0.001f);
                            jidx = __float_as_int(p.w);
                        }
                        unsigned bal = __ballot_sync(0xffffffffu, hit);
                        if (hit) {
                            int slot = cur + __popc(bal & ((1u << lane) - 1u));
                            if (slot < MAXPA) sjw[slot] = jidx;
                        }
                        cur += __popc(bal);
                    }
                }
        }
        __syncwarp();
        int k = min(cur, MAXPA);
        // rank sort by image idx (unique) -> exact reference order
        int vals[6], rnks[6];
        int nn = 0;
        for (int i2 = lane; i2 < k; i2 += 32) {
            int v = sjw[i2];
            int r = 0;
            for (int q = 0; q < k; q++) r += (sjw[q] < v);
            vals[nn] = v;
            rnks[nn] = r;
            nn++;
        }
        __syncwarp();
        for (int q = 0; q < nn; q++) sjw[rnks[q]] = vals[q];
        if (w < N && lane == 0) g_cnt[w] = k;
    }
    gbar(++gen);  // B1: counts complete

    // ================= PHASE C: offsets (redundant scan) + write =================
    {
        int cA[4];
        int myv = 0;
        int a0 = t * 4;
#pragma unroll
        for (int q = 0; q < 4; q++) {
            int a = a0 + q;
            cA[q] = (a < N) ? g_cnt[a] : 0;
            myv += cA[q];
        }
        int run = scanExcl1024(myv, stmp, lane, wid);
#pragma unroll
        for (int q = 0; q < 4; q++) {
            int a = a0 + q;
            if (a < N && (a & (NBLK - 1)) == b) sWoff[a >> 7] = run;
            run += cA[q];
        }
        __syncthreads();

        int w = wid * NBLK + b;
        if (w < N) {
            int off = sWoff[wid];
            int k = min(g_cnt[w], MAXPA);
            int* sjw = sj + wid * MAXPA;
            float fi = (float)w;
            for (int r = lane; r < k; r += 32) {
                int idx = sjw[r];
                int s = idx / N;
                int a = idx - s * N;
                int pos = off + r;
                out[pos] = fi;
                out[P + pos] = (float)a;
                out[2 * P + 3 * pos + 0] = sshifts[s * 3 + 0];
                out[2 * P + 3 * pos + 1] = sshifts[s * 3 + 1];
                out[2 * P + 3 * pos + 2] = sshifts[s * 3 + 2];
            }
        }
    }
}

// ---------------- launch ----------------
extern "C" void kernel_launch(void* const* d_in, const int* in_sizes, int n_in,
                              void* d_out, int out_size) {
    const int* period = (const int*)d_in[0];
    const float* coords = (const float*)d_in[1];
    const float* cell = (const float*)d_in[2];
    const float* mass = (const float*)d_in[3];
    float* out = (float*)d_out;

    int N = in_sizes[1] / 3;
    int P = out_size / 5;

    int smem = 32768 + 3 * 4 * N + (NCELL + 8) * 4 + 128;
    cudaFuncSetAttribute(k_all, cudaFuncAttributeMaxDynamicSharedMemorySize, smem);
    k_all<<<NBLK, NTHR, smem>>>(cell, period, coords, mass, N, P, out);
}

// round 7
// speedup vs baseline: 1.4224x; 1.4224x over previous
#include <cuda_runtime.h>
#include <math.h>

#define NBLK 128
#define NTHR 1024
#define MAXN 4096
#define MAXS 27
#define MAXC (MAXS * MAXN)
#define NGRID 10
#define NCELL (NGRID * NGRID * NGRID)
#define MAXPA 192

__device__ float4 g_bimg4[MAXC];
__device__ int    g_ccnt[NCELL];    // zero at load; re-zeroed post-B1 every launch
__device__ int    g_cfill[NCELL];   // zero at load; re-zeroed post-B1 every launch
__device__ int    g_cnt[MAXN];
__device__ unsigned g_barcnt, g_bargen;

#define MUL(a, b) __fmul_rn((a), (b))
#define ADD(a, b) __fadd_rn((a), (b))
#define SUB(a, b) __fsub_rn((a), (b))
#define DIV(a, b) __fdiv_rn((a), (b))

__device__ __forceinline__ unsigned fkey(float f) {
    unsigned u = __float_as_uint(f);
    return (u & 0x80000000u) ? ~u : (u | 0x80000000u);
}
__device__ __forceinline__ float fdec(unsigned k) {
    unsigned u = (k & 0x80000000u) ? (k & 0x7fffffffu) : ~k;
    return __uint_as_float(u);
}

// grid barrier: all NBLK blocks co-resident (128 blocks, 1/SM)
__device__ __forceinline__ void gbar(unsigned target) {
    __syncthreads();
    if (threadIdx.x == 0) {
        __threadfence();
        unsigned a = atomicAdd(&g_barcnt, 1u);
        if (a == NBLK - 1u) {
            g_barcnt = 0u;
            __threadfence();
            atomicExch(&g_bargen, target);
        } else {
            while ((int)(*(volatile unsigned*)&g_bargen - target) < 0) { }
            __threadfence();
        }
    }
    __syncthreads();
}

// exclusive scan over 1024 threads; 3 syncthreads
__device__ __forceinline__ int scanExcl1024(int v, int* stmp, int lane, int wid) {
    __syncthreads();
    int x = v;
#pragma unroll
    for (int o = 1; o < 32; o <<= 1) {
        int y = __shfl_up_sync(0xffffffffu, x, o);
        if (lane >= o) x += y;
    }
    if (lane == 31) stmp[wid] = x;
    __syncthreads();
    if (wid == 0) {
        int s = stmp[lane];
#pragma unroll
        for (int o = 1; o < 32; o <<= 1) {
            int y = __shfl_up_sync(0xffffffffu, s, o);
            if (lane >= o) s += y;
        }
        stmp[lane] = s;
    }
    __syncthreads();
    int base = wid ? stmp[wid - 1] : 0;
    return base + x - v;
}

extern __shared__ char dynsmem[];

__global__ __launch_bounds__(NTHR, 1)
void k_all(const float* __restrict__ cell, const int* __restrict__ period,
           const float* __restrict__ coords, const float* __restrict__ mass,
           int N, int P, float* __restrict__ out) {
    __shared__ float sinv[9], sfrac0[3], sshifts[MAXS * 3];
    __shared__ float scom[3], sminc[3], smaxc[3];
    __shared__ int   sS;
    __shared__ int   stmp[33];
    __shared__ unsigned skey[32];
    __shared__ unsigned sredmin[3], sredmax[3];
    __shared__ int   sWoff[32];

    // dynamic shared carve-up
    double* sd    = (double*)dynsmem;                 // 32768B COM tree (phase A)
    int*    sj    = (int*)dynsmem;                    // alias (search/write): 32*192*4 = 24576B
    float*  s_wx  = (float*)(dynsmem + 32768);
    float*  s_wy  = s_wx + N;
    float*  s_wz  = s_wy + N;
    int*    scoff = (int*)(dynsmem + 32768 + 3 * 4 * N);

    const int t = threadIdx.x, b = blockIdx.x;
    const int lane = t & 31, wid = t >> 5;
    const int gt = b * NTHR + t;
    const int GT = NBLK * NTHR;
    unsigned gen = *(volatile unsigned*)&g_bargen;

    // ================= PHASE A =================
    if (t == 0) {
        float m00 = cell[0], m01 = cell[1], m02 = cell[2];
        float m10 = cell[3], m11 = cell[4], m12 = cell[5];
        float m20 = cell[6], m21 = cell[7], m22 = cell[8];
        float c00 = SUB(MUL(m11, m22), MUL(m12, m21));
        float c10 = SUB(MUL(m12, m20), MUL(m10, m22));
        float c20 = SUB(MUL(m10, m21), MUL(m11, m20));
        float det = ADD(ADD(MUL(m00, c00), MUL(m01, c10)), MUL(m02, c20));
        sinv[0] = DIV(c00, det);
        sinv[1] = DIV(SUB(MUL(m02, m21), MUL(m01, m22)), det);
        sinv[2] = DIV(SUB(MUL(m01, m12), MUL(m02, m11)), det);
        sinv[3] = DIV(c10, det);
        sinv[4] = DIV(SUB(MUL(m00, m22), MUL(m02, m20)), det);
        sinv[5] = DIV(SUB(MUL(m02, m10), MUL(m00, m12)), det);
        sinv[6] = DIV(c20, det);
        sinv[7] = DIV(SUB(MUL(m01, m20), MUL(m00, m21)), det);
        sinv[8] = DIV(SUB(MUL(m00, m11), MUL(m01, m10)), det);
        float x0 = coords[0], y0 = coords[1], z0 = coords[2];
        for (int d = 0; d < 3; d++)
            sfrac0[d] = ADD(ADD(MUL(x0, sinv[0 + d]), MUL(y0, sinv[3 + d])), MUL(z0, sinv[6 + d]));
        int nrep[3];
        for (int i = 0; i < 3; i++) {
            float r = DIV(5.0f, fabsf(cell[0 + i]));
            float r1 = DIV(5.0f, fabsf(cell[3 + i]));
            float r2 = DIV(5.0f, fabsf(cell[6 + i]));
            if (r1 < r) r = r1;
            if (r2 < r) r = r2;
            nrep[i] = (int)ceilf(r) * period[i];
        }
        int idx = 0;
        for (int a = -nrep[0]; a <= nrep[0]; a++)
            for (int bb = -nrep[1]; bb <= nrep[1]; bb++)
                for (int c = -nrep[2]; c <= nrep[2]; c++) {
                    if (idx < MAXS) {
                        float fa = (float)a, fb = (float)bb, fc = (float)c;
                        for (int d = 0; d < 3; d++)
                            sshifts[idx * 3 + d] =
                                ADD(ADD(MUL(fa, cell[0 + d]), MUL(fb, cell[3 + d])), MUL(fc, cell[6 + d]));
                    }
                    idx++;
                }
        sS = (idx > MAXS) ? MAXS : idx;
    }
    __syncthreads();
    const int S = sS;
    const int NS = S * N;

    // wrap ALL atoms into shared (redundant per block; bit-identical everywhere)
    for (int i = t; i < N; i += NTHR) {
        float x = coords[i * 3 + 0], y = coords[i * 3 + 1], z = coords[i * 3 + 2];
        float f[3];
        for (int d = 0; d < 3; d++)
            f[d] = ADD(ADD(MUL(x, sinv[0 + d]), MUL(y, sinv[3 + d])), MUL(z, sinv[6 + d]));
        for (int d = 0; d < 3; d++)
            f[d] = SUB(f[d], rintf(SUB(f[d], sfrac0[d])));
        s_wx[i] = ADD(ADD(MUL(f[0], cell[0]), MUL(f[1], cell[3])), MUL(f[2], cell[6]));
        s_wy[i] = ADD(ADD(MUL(f[0], cell[1]), MUL(f[1], cell[4])), MUL(f[2], cell[7]));
        s_wz[i] = ADD(ADD(MUL(f[0], cell[2]), MUL(f[1], cell[5])), MUL(f[2], cell[8]));
    }
    __syncthreads();

    // COM: bit-identical accumulation order to R1-R6
    {
        double s0 = 0.0, s1 = 0.0, s2 = 0.0, s3 = 0.0;
        for (int i = t; i < N; i += NTHR) {
            double m = (double)mass[i];
            s0 += m * (double)s_wx[i];
            s1 += m * (double)s_wy[i];
            s2 += m * (double)s_wz[i];
            s3 += m;
        }
        sd[t] = s0; sd[1024 + t] = s1; sd[2048 + t] = s2; sd[3072 + t] = s3;
        __syncthreads();
        for (int off = 512; off > 0; off >>= 1) {
            if (t < off) {
                sd[t] += sd[t + off];
                sd[1024 + t] += sd[1024 + t + off];
                sd[2048 + t] += sd[2048 + t + off];
                sd[3072 + t] += sd[3072 + t + off];
            }
            __syncthreads();
        }
        if (t == 0) {
            float sm = (float)sd[3072];
            scom[0] = DIV((float)sd[0], sm);
            scom[1] = DIV((float)sd[1024], sm);
            scom[2] = DIV((float)sd[2048], sm);
        }
        __syncthreads();
    }

    // min/max over centered coords (exact, order-free key reductions)
    {
        unsigned kmn[3] = {~0u, ~0u, ~0u}, kmx[3] = {0u, 0u, 0u};
        for (int i = t; i < N; i += NTHR) {
            unsigned k0 = fkey(SUB(s_wx[i], scom[0]));
            unsigned k1 = fkey(SUB(s_wy[i], scom[1]));
            unsigned k2 = fkey(SUB(s_wz[i], scom[2]));
            kmn[0] = min(kmn[0], k0); kmx[0] = max(kmx[0], k0);
            kmn[1] = min(kmn[1], k1); kmx[1] = max(kmx[1], k1);
            kmn[2] = min(kmn[2], k2); kmx[2] = max(kmx[2], k2);
        }
#pragma unroll
        for (int d = 0; d < 3; d++) {
            unsigned v = kmn[d];
#pragma unroll
            for (int o = 16; o; o >>= 1) v = min(v, __shfl_xor_sync(0xffffffffu, v, o));
            if (lane == 0) skey[wid] = v;
            __syncthreads();
            if (wid == 0) {
                unsigned s = skey[lane];
#pragma unroll
                for (int o = 16; o; o >>= 1) s = min(s, __shfl_xor_sync(0xffffffffu, s, o));
                if (lane == 0) sredmin[d] = s;
            }
            __syncthreads();
            v = kmx[d];
#pragma unroll
            for (int o = 16; o; o >>= 1) v = max(v, __shfl_xor_sync(0xffffffffu, v, o));
            if (lane == 0) skey[wid] = v;
            __syncthreads();
            if (wid == 0) {
                unsigned s = skey[lane];
#pragma unroll
                for (int o = 16; o; o >>= 1) s = max(s, __shfl_xor_sync(0xffffffffu, s, o));
                if (lane == 0) sredmax[d] = s;
            }
            __syncthreads();
        }
        if (t < 3) {
            float mn = SUB(SUB(fdec(sredmin[t]), 5.0f), 1e-6f);
            sminc[t] = mn;
            smaxc[t] = ADD(SUB(fdec(sredmax[t]), mn), 5.0f);
        }
        __syncthreads();
    }

    // transform in place: s_w* := c2
    for (int i = t; i < N; i += NTHR) {
        s_wx[i] = SUB(SUB(s_wx[i], scom[0]), sminc[0]);
        s_wy[i] = SUB(SUB(s_wy[i], scom[1]), sminc[1]);
        s_wz[i] = SUB(SUB(s_wz[i], scom[2]), sminc[2]);
    }
    __syncthreads();

    // PARTITIONED histogram over images -> global g_ccnt (R4-style, no redundancy)
    const float maxc0 = smaxc[0], maxc1 = smaxc[1], maxc2 = smaxc[2];
    for (int idx = gt; idx < NS; idx += GT) {
        int s = idx / N;
        int a = idx - s * N;
        float v0 = ADD(s_wx[a], sshifts[s * 3 + 0]);
        float v1 = ADD(s_wy[a], sshifts[s * 3 + 1]);
        float v2 = ADD(s_wz[a], sshifts[s * 3 + 2]);
        if ((v0 > 0.f) && (v0 < maxc0) && (v1 > 0.f) && (v1 < maxc1) &&
            (v2 > 0.f) && (v2 < maxc2)) {
            int cx = min(max((int)floorf(DIV(v0, 5.0f)), 0), NGRID - 1);
            int cy = min(max((int)floorf(DIV(v1, 5.0f)), 0), NGRID - 1);
            int cz = min(max((int)floorf(DIV(v2, 5.0f)), 0), NGRID - 1);
            atomicAdd(&g_ccnt[cx + NGRID * (cy + NGRID * cz)], 1);
        }
    }
    gbar(++gen);  // B0: histogram complete

    // block-local scan of g_ccnt -> scoff (identical in every block)
    {
        int cv = (t < NCELL) ? g_ccnt[t] : 0;
        int ce = scanExcl1024(cv, stmp, lane, wid);
        if (t <= NCELL + 4) scoff[t] = ce;   // t >= NCELL carry the total
        __syncthreads();
    }

    // PARTITIONED scatter of images into global buckets
    for (int idx = gt; idx < NS; idx += GT) {
        int s = idx / N;
        int a = idx - s * N;
        float v0 = ADD(s_wx[a], sshifts[s * 3 + 0]);
        float v1 = ADD(s_wy[a], sshifts[s * 3 + 1]);
        float v2 = ADD(s_wz[a], sshifts[s * 3 + 2]);
        if ((v0 > 0.f) && (v0 < maxc0) && (v1 > 0.f) && (v1 < maxc1) &&
            (v2 > 0.f) && (v2 < maxc2)) {
            int cx = min(max((int)floorf(DIV(v0, 5.0f)), 0), NGRID - 1);
            int cy = min(max((int)floorf(DIV(v1, 5.0f)), 0), NGRID - 1);
            int cz = min(max((int)floorf(DIV(v2, 5.0f)), 0), NGRID - 1);
            int c = cx + NGRID * (cy + NGRID * cz);
            int pos = scoff[c] + atomicAdd(&g_cfill[c], 1);
            g_bimg4[pos] = make_float4(v0, v1, v2, __int_as_float(idx));
        }
    }
    gbar(++gen);  // B1: buckets complete

    // re-zero globals for next replay (not read again this launch)
    for (int i = gt; i < NCELL; i += GT) { g_ccnt[i] = 0; g_cfill[i] = 0; }

    // ================= PHASE B: flattened per-atom search + in-warp rank sort ==========
    {
        int w = wid * NBLK + b;
        int* sjw = sj + wid * MAXPA;
        int cur = 0;
        if (w < N) {
            float cx = s_wx[w], cy = s_wy[w], cz = s_wz[w];
            int ax = (int)floorf(DIV(cx, 5.0f));
            int ay = (int)floorf(DIV(cy, 5.0f));
            int az = (int)floorf(DIV(cz, 5.0f));
            // 9 merged x-rows -> flattened candidate stream
            int rsv[9], rlv[9];
#pragma unroll
            for (int q = 0; q < 9; q++) {
                int dz = q / 3 - 1, dy = q % 3 - 1;
                int row = (ax - 1) + NGRID * ((ay + dy) + NGRID * (az + dz));
                int sq = scoff[row];
                rsv[q] = sq;
                rlv[q] = scoff[row + 3] - sq;
            }
            int p1 = rlv[0];
            int p2 = p1 + rlv[1];
            int p3 = p2 + rlv[2];
            int p4 = p3 + rlv[3];
            int p5 = p4 + rlv[4];
            int p6 = p5 + rlv[5];
            int p7 = p6 + rlv[6];
            int p8 = p7 + rlv[7];
            int p9 = p8 + rlv[8];
            int b0 = rsv[0];
            int b1 = rsv[1] - p1;
            int b2 = rsv[2] - p2;
            int b3 = rsv[3] - p3;
            int b4 = rsv[4] - p4;
            int b5 = rsv[5] - p5;
            int b6 = rsv[6] - p6;
            int b7 = rsv[7] - p7;
            int b8 = rsv[8] - p8;
            for (int f0 = 0; f0 < p9; f0 += 32) {
                int f = f0 + lane;
                bool act = (f < p9);
                int base = (f < p1) ? b0
                         : (f < p2) ? b1
                         : (f < p3) ? b2
                         : (f < p4) ? b3
                         : (f < p5) ? b4
                         : (f < p6) ? b5
                         : (f < p7) ? b6
                         : (f < p8) ? b7
                         : b8;
                bool hit = false;
                int jidx = 0;
                if (act) {
                    float4 p = g_bimg4[f + base];
                    float ddx = SUB(cx, p.x);
                    float ddy = SUB(cy, p.y);
                    float ddz = SUB(cz, p.z);
                    float r2 = ADD(ADD(MUL(ddx, ddx), MUL(ddy, ddy)), MUL(ddz, ddz));
                    float dd = __fsqrt_rn(r2);
                    hit = (dd < 5.0f) && (dd > 0.001f);
                    jidx = __float_as_int(p.w);
                }
                unsigned bal = __ballot_sync(0xffffffffu, hit);
                if (hit) {
                    int slot = cur + __popc(bal & ((1u << lane) - 1u));
                    if (slot < MAXPA) sjw[slot] = jidx;
                }
                cur += __popc(bal);
            }
        }
        __syncwarp();
        int k = min(cur, MAXPA);
        // rank sort by image idx (unique) -> exact reference order
        int vals[6], rnks[6];
        int nn = 0;
        for (int i2 = lane; i2 < k; i2 += 32) {
            int v = sjw[i2];
            int r = 0;
            for (int q = 0; q < k; q++) r += (sjw[q] < v);
            vals[nn] = v;
            rnks[nn] = r;
            nn++;
        }
        __syncwarp();
        for (int q = 0; q < nn; q++) sjw[rnks[q]] = vals[q];
        if (w < N && lane == 0) g_cnt[w] = k;
    }
    gbar(++gen);  // B2: counts complete

    // ================= PHASE C: offsets (redundant scan) + write =================
    {
        int cA[4];
        int myv = 0;
        int a0 = t * 4;
#pragma unroll
        for (int q = 0; q < 4; q++) {
            int a = a0 + q;
            cA[q] = (a < N) ? g_cnt[a] : 0;
            myv += cA[q];
        }
        int run = scanExcl1024(myv, stmp, lane, wid);
#pragma unroll
        for (int q = 0; q < 4; q++) {
            int a = a0 + q;
            if (a < N && (a & (NBLK - 1)) == b) sWoff[a >> 7] = run;
            run += cA[q];
        }
        __syncthreads();

        int w = wid * NBLK + b;
        if (w < N) {
            int off = sWoff[wid];
            int k = min(g_cnt[w], MAXPA);
            int* sjw = sj + wid * MAXPA;
            float fi = (float)w;
            for (int r = lane; r < k; r += 32) {
                int idx = sjw[r];
                int s = idx / N;
                int a = idx - s * N;
                int pos = off + r;
                out[pos] = fi;
                out[P + pos] = (float)a;
                out[2 * P + 3 * pos + 0] = sshifts[s * 3 + 0];
                out[2 * P + 3 * pos + 1] = sshifts[s * 3 + 1];
                out[2 * P + 3 * pos + 2] = sshifts[s * 3 + 2];
            }
        }
    }
}

// ---------------- launch ----------------
extern "C" void kernel_launch(void* const* d_in, const int* in_sizes, int n_in,
                              void* d_out, int out_size) {
    const int* period = (const int*)d_in[0];
    const float* coords = (const float*)d_in[1];
    const float* cell = (const float*)d_in[2];
    const float* mass = (const float*)d_in[3];
    float* out = (float*)d_out;

    int N = in_sizes[1] / 3;
    int P = out_size / 5;

    int smem = 32768 + 3 * 4 * N + (NCELL + 8) * 4 + 128;
    cudaFuncSetAttribute(k_all, cudaFuncAttributeMaxDynamicSharedMemorySize, smem);
    k_all<<<NBLK, NTHR, smem>>>(cell, period, coords, mass, N, P, out);
}

// round 8
// speedup vs baseline: 1.4259x; 1.0024x over previous
#include <cuda_runtime.h>
#include <math.h>

#define NBLK 128
#define NTHR 1024
#define MAXN 4096
#define MAXS 27
#define MAXC (MAXS * MAXN)
#define NGRID 10
#define NCELL (NGRID * NGRID * NGRID)
#define MAXPA 192

__device__ float4 g_bimg4[MAXC];
__device__ int    g_ccnt[NCELL];    // zero at load; re-zeroed post-B1 every launch
__device__ int    g_cfill[NCELL];   // zero at load; re-zeroed post-B1 every launch
__device__ int    g_cnt[MAXN];
__device__ unsigned g_barcnt, g_bargen;

#define MUL(a, b) __fmul_rn((a), (b))
#define ADD(a, b) __fadd_rn((a), (b))
#define SUB(a, b) __fsub_rn((a), (b))
#define DIV(a, b) __fdiv_rn((a), (b))

__device__ __forceinline__ unsigned fkey(float f) {
    unsigned u = __float_as_uint(f);
    return (u & 0x80000000u) ? ~u : (u | 0x80000000u);
}
__device__ __forceinline__ float fdec(unsigned k) {
    unsigned u = (k & 0x80000000u) ? (k & 0x7fffffffu) : ~k;
    return __uint_as_float(u);
}

// grid barrier: all NBLK blocks co-resident (128 blocks, 1/SM)
__device__ __forceinline__ void gbar(unsigned target) {
    __syncthreads();
    if (threadIdx.x == 0) {
        __threadfence();
        unsigned a = atomicAdd(&g_barcnt, 1u);
        if (a == NBLK - 1u) {
            g_barcnt = 0u;
            __threadfence();
            atomicExch(&g_bargen, target);
        } else {
            while ((int)(*(volatile unsigned*)&g_bargen - target) < 0) { }
            __threadfence();
        }
    }
    __syncthreads();
}

// exclusive scan over 1024 threads; 3 syncthreads
__device__ __forceinline__ int scanExcl1024(int v, int* stmp, int lane, int wid) {
    __syncthreads();
    int x = v;
#pragma unroll
    for (int o = 1; o < 32; o <<= 1) {
        int y = __shfl_up_sync(0xffffffffu, x, o);
        if (lane >= o) x += y;
    }
    if (lane == 31) stmp[wid] = x;
    __syncthreads();
    if (wid == 0) {
        int s = stmp[lane];
#pragma unroll
        for (int o = 1; o < 32; o <<= 1) {
            int y = __shfl_up_sync(0xffffffffu, s, o);
            if (lane >= o) s += y;
        }
        stmp[lane] = s;
    }
    __syncthreads();
    int base = wid ? stmp[wid - 1] : 0;
    return base + x - v;
}

extern __shared__ char dynsmem[];

__global__ __launch_bounds__(NTHR, 1)
void k_all(const float* __restrict__ cell, const int* __restrict__ period,
           const float* __restrict__ coords, const float* __restrict__ mass,
           int N, int P, float* __restrict__ out) {
    __shared__ float sinv[9], sfrac0[3], sshifts[MAXS * 3];
    __shared__ float scom[3], sminc[3], smaxc[3];
    __shared__ int   sS;
    __shared__ int   stmp[33];
    __shared__ unsigned skey6[32][6];
    __shared__ int   sWoff[32];

    // dynamic shared carve-up
    double* sd    = (double*)dynsmem;                 // 32768B COM tree (phase A)
    int*    sj    = (int*)dynsmem;                    // alias (search/write): 32*192*4 = 24576B
    float*  s_wx  = (float*)(dynsmem + 32768);
    float*  s_wy  = s_wx + N;
    float*  s_wz  = s_wy + N;
    int*    scoff = (int*)(dynsmem + 32768 + 3 * 4 * N);

    const int t = threadIdx.x, b = blockIdx.x;
    const int lane = t & 31, wid = t >> 5;
    const int gt = b * NTHR + t;
    const int GT = NBLK * NTHR;
    unsigned gen = *(volatile unsigned*)&g_bargen;

    // ================= PHASE A =================
    if (t == 0) {
        float m00 = cell[0], m01 = cell[1], m02 = cell[2];
        float m10 = cell[3], m11 = cell[4], m12 = cell[5];
        float m20 = cell[6], m21 = cell[7], m22 = cell[8];
        float c00 = SUB(MUL(m11, m22), MUL(m12, m21));
        float c10 = SUB(MUL(m12, m20), MUL(m10, m22));
        float c20 = SUB(MUL(m10, m21), MUL(m11, m20));
        float det = ADD(ADD(MUL(m00, c00), MUL(m01, c10)), MUL(m02, c20));
        sinv[0] = DIV(c00, det);
        sinv[1] = DIV(SUB(MUL(m02, m21), MUL(m01, m22)), det);
        sinv[2] = DIV(SUB(MUL(m01, m12), MUL(m02, m11)), det);
        sinv[3] = DIV(c10, det);
        sinv[4] = DIV(SUB(MUL(m00, m22), MUL(m02, m20)), det);
        sinv[5] = DIV(SUB(MUL(m02, m10), MUL(m00, m12)), det);
        sinv[6] = DIV(c20, det);
        sinv[7] = DIV(SUB(MUL(m01, m20), MUL(m00, m21)), det);
        sinv[8] = DIV(SUB(MUL(m00, m11), MUL(m01, m10)), det);
        float x0 = coords[0], y0 = coords[1], z0 = coords[2];
        for (int d = 0; d < 3; d++)
            sfrac0[d] = ADD(ADD(MUL(x0, sinv[0 + d]), MUL(y0, sinv[3 + d])), MUL(z0, sinv[6 + d]));
        int nrep[3];
        for (int i = 0; i < 3; i++) {
            float r = DIV(5.0f, fabsf(cell[0 + i]));
            float r1 = DIV(5.0f, fabsf(cell[3 + i]));
            float r2 = DIV(5.0f, fabsf(cell[6 + i]));
            if (r1 < r) r = r1;
            if (r2 < r) r = r2;
            nrep[i] = (int)ceilf(r) * period[i];
        }
        int idx = 0;
        for (int a = -nrep[0]; a <= nrep[0]; a++)
            for (int bb = -nrep[1]; bb <= nrep[1]; bb++)
                for (int c = -nrep[2]; c <= nrep[2]; c++) {
                    if (idx < MAXS) {
                        float fa = (float)a, fb = (float)bb, fc = (float)c;
                        for (int d = 0; d < 3; d++)
                            sshifts[idx * 3 + d] =
                                ADD(ADD(MUL(fa, cell[0 + d]), MUL(fb, cell[3 + d])), MUL(fc, cell[6 + d]));
                    }
                    idx++;
                }
        sS = (idx > MAXS) ? MAXS : idx;
    }
    __syncthreads();
    const int S = sS;
    const int NS = S * N;

    // wrap ALL atoms into shared (redundant per block; bit-identical everywhere)
    for (int i = t; i < N; i += NTHR) {
        float x = coords[i * 3 + 0], y = coords[i * 3 + 1], z = coords[i * 3 + 2];
        float f[3];
        for (int d = 0; d < 3; d++)
            f[d] = ADD(ADD(MUL(x, sinv[0 + d]), MUL(y, sinv[3 + d])), MUL(z, sinv[6 + d]));
        for (int d = 0; d < 3; d++)
            f[d] = SUB(f[d], rintf(SUB(f[d], sfrac0[d])));
        s_wx[i] = ADD(ADD(MUL(f[0], cell[0]), MUL(f[1], cell[3])), MUL(f[2], cell[6]));
        s_wy[i] = ADD(ADD(MUL(f[0], cell[1]), MUL(f[1], cell[4])), MUL(f[2], cell[7]));
        s_wz[i] = ADD(ADD(MUL(f[0], cell[2]), MUL(f[1], cell[5])), MUL(f[2], cell[8]));
    }
    __syncthreads();

    // COM: accumulation + tree levels 512..32 in shared, last 5 levels via shfl_down.
    // Pairing (t, t+off) is preserved exactly -> bit-identical to R1-R7.
    {
        double s0 = 0.0, s1 = 0.0, s2 = 0.0, s3 = 0.0;
        for (int i = t; i < N; i += NTHR) {
            double m = (double)mass[i];
            s0 += m * (double)s_wx[i];
            s1 += m * (double)s_wy[i];
            s2 += m * (double)s_wz[i];
            s3 += m;
        }
        sd[t] = s0; sd[1024 + t] = s1; sd[2048 + t] = s2; sd[3072 + t] = s3;
        __syncthreads();
#pragma unroll
        for (int off = 512; off >= 32; off >>= 1) {
            if (t < off) {
                sd[t] += sd[t + off];
                sd[1024 + t] += sd[1024 + t + off];
                sd[2048 + t] += sd[2048 + t + off];
                sd[3072 + t] += sd[3072 + t + off];
            }
            __syncthreads();
        }
        if (wid == 0) {
            double x0 = sd[lane], x1 = sd[1024 + lane], x2 = sd[2048 + lane], x3 = sd[3072 + lane];
#pragma unroll
            for (int off = 16; off >= 1; off >>= 1) {
                x0 += __shfl_down_sync(0xffffffffu, x0, off);
                x1 += __shfl_down_sync(0xffffffffu, x1, off);
                x2 += __shfl_down_sync(0xffffffffu, x2, off);
                x3 += __shfl_down_sync(0xffffffffu, x3, off);
            }
            if (lane == 0) {
                float sm = (float)x3;
                scom[0] = DIV((float)x0, sm);
                scom[1] = DIV((float)x1, sm);
                scom[2] = DIV((float)x2, sm);
            }
        }
        __syncthreads();
    }

    // min/max over centered coords: single pass, 6 keys reduced together (order-free)
    {
        unsigned kmn[3] = {~0u, ~0u, ~0u}, kmx[3] = {0u, 0u, 0u};
        for (int i = t; i < N; i += NTHR) {
            unsigned k0 = fkey(SUB(s_wx[i], scom[0]));
            unsigned k1 = fkey(SUB(s_wy[i], scom[1]));
            unsigned k2 = fkey(SUB(s_wz[i], scom[2]));
            kmn[0] = min(kmn[0], k0); kmx[0] = max(kmx[0], k0);
            kmn[1] = min(kmn[1], k1); kmx[1] = max(kmx[1], k1);
            kmn[2] = min(kmn[2], k2); kmx[2] = max(kmx[2], k2);
        }
#pragma unroll
        for (int o = 16; o; o >>= 1) {
#pragma unroll
            for (int d = 0; d < 3; d++) {
                kmn[d] = min(kmn[d], __shfl_xor_sync(0xffffffffu, kmn[d], o));
                kmx[d] = max(kmx[d], __shfl_xor_sync(0xffffffffu, kmx[d], o));
            }
        }
        if (lane == 0) {
#pragma unroll
            for (int d = 0; d < 3; d++) {
                skey6[wid][d] = kmn[d];
                skey6[wid][3 + d] = kmx[d];
            }
        }
        __syncthreads();
        if (wid == 0) {
            unsigned vn0 = skey6[lane][0], vn1 = skey6[lane][1], vn2 = skey6[lane][2];
            unsigned vx0 = skey6[lane][3], vx1 = skey6[lane][4], vx2 = skey6[lane][5];
#pragma unroll
            for (int o = 16; o; o >>= 1) {
                vn0 = min(vn0, __shfl_xor_sync(0xffffffffu, vn0, o));
                vn1 = min(vn1, __shfl_xor_sync(0xffffffffu, vn1, o));
                vn2 = min(vn2, __shfl_xor_sync(0xffffffffu, vn2, o));
                vx0 = max(vx0, __shfl_xor_sync(0xffffffffu, vx0, o));
                vx1 = max(vx1, __shfl_xor_sync(0xffffffffu, vx1, o));
                vx2 = max(vx2, __shfl_xor_sync(0xffffffffu, vx2, o));
            }
            if (lane == 0) {
                float mn0 = SUB(SUB(fdec(vn0), 5.0f), 1e-6f);
                float mn1 = SUB(SUB(fdec(vn1), 5.0f), 1e-6f);
                float mn2 = SUB(SUB(fdec(vn2), 5.0f), 1e-6f);
                sminc[0] = mn0; sminc[1] = mn1; sminc[2] = mn2;
                smaxc[0] = ADD(SUB(fdec(vx0), mn0), 5.0f);
                smaxc[1] = ADD(SUB(fdec(vx1), mn1), 5.0f);
                smaxc[2] = ADD(SUB(fdec(vx2), mn2), 5.0f);
            }
        }
        __syncthreads();
    }

    // transform in place: s_w* := c2
    for (int i = t; i < N; i += NTHR) {
        s_wx[i] = SUB(SUB(s_wx[i], scom[0]), sminc[0]);
        s_wy[i] = SUB(SUB(s_wy[i], scom[1]), sminc[1]);
        s_wz[i] = SUB(SUB(s_wz[i], scom[2]), sminc[2]);
    }
    __syncthreads();

    // ONE image per thread (NS <= MAXS*MAXN = 110592 <= GT = 131072).
    // Compute once, keep in registers across B0; histogram into global g_ccnt.
    const float maxc0 = smaxc[0], maxc1 = smaxc[1], maxc2 = smaxc[2];
    bool  myflag = false;
    int   mycell = 0;
    float v0 = 0.f, v1 = 0.f, v2 = 0.f;
    if (gt < NS) {
        int s = gt / N;
        int a = gt - s * N;
        v0 = ADD(s_wx[a], sshifts[s * 3 + 0]);
        v1 = ADD(s_wy[a], sshifts[s * 3 + 1]);
        v2 = ADD(s_wz[a], sshifts[s * 3 + 2]);
        myflag = (v0 > 0.f) && (v0 < maxc0) && (v1 > 0.f) && (v1 < maxc1) &&
                 (v2 > 0.f) && (v2 < maxc2);
        if (myflag) {
            int cx = min(max((int)floorf(DIV(v0, 5.0f)), 0), NGRID - 1);
            int cy = min(max((int)floorf(DIV(v1, 5.0f)), 0), NGRID - 1);
            int cz = min(max((int)floorf(DIV(v2, 5.0f)), 0), NGRID - 1);
            mycell = cx + NGRID * (cy + NGRID * cz);
            atomicAdd(&g_ccnt[mycell], 1);
        }
    }
    gbar(++gen);  // B0: histogram complete

    // block-local scan of g_ccnt -> scoff (identical in every block)
    {
        int cv = (t < NCELL) ? g_ccnt[t] : 0;
        int ce = scanExcl1024(cv, stmp, lane, wid);
        if (t <= NCELL + 4) scoff[t] = ce;   // t >= NCELL carry the total
        __syncthreads();
    }

    // scatter own image from registers into global buckets
    if (myflag) {
        int pos = scoff[mycell] + atomicAdd(&g_cfill[mycell], 1);
        g_bimg4[pos] = make_float4(v0, v1, v2, __int_as_float(gt));
    }
    gbar(++gen);  // B1: buckets complete

    // re-zero globals for next replay (not read again this launch)
    for (int i = gt; i < NCELL; i += GT) { g_ccnt[i] = 0; g_cfill[i] = 0; }

    // ================= PHASE B: flattened per-atom search + in-warp rank sort ==========
    {
        int w = wid * NBLK + b;
        int* sjw = sj + wid * MAXPA;
        int cur = 0;
        if (w < N) {
            float cx = s_wx[w], cy = s_wy[w], cz = s_wz[w];
            int ax = (int)floorf(DIV(cx, 5.0f));
            int ay = (int)floorf(DIV(cy, 5.0f));
            int az = (int)floorf(DIV(cz, 5.0f));
            // 9 merged x-rows -> flattened candidate stream
            int rsv[9], rlv[9];
#pragma unroll
            for (int q = 0; q < 9; q++) {
                int dz = q / 3 - 1, dy = q % 3 - 1;
                int row = (ax - 1) + NGRID * ((ay + dy) + NGRID * (az + dz));
                int sq = scoff[row];
                rsv[q] = sq;
                rlv[q] = scoff[row + 3] - sq;
            }
            int p1 = rlv[0];
            int p2 = p1 + rlv[1];
            int p3 = p2 + rlv[2];
            int p4 = p3 + rlv[3];
            int p5 = p4 + rlv[4];
            int p6 = p5 + rlv[5];
            int p7 = p6 + rlv[6];
            int p8 = p7 + rlv[7];
            int p9 = p8 + rlv[8];
            int b0 = rsv[0];
            int b1 = rsv[1] - p1;
            int b2 = rsv[2] - p2;
            int b3 = rsv[3] - p3;
            int b4 = rsv[4] - p4;
            int b5 = rsv[5] - p5;
            int b6 = rsv[6] - p6;
            int b7 = rsv[7] - p7;
            int b8 = rsv[8] - p8;
            for (int f0 = 0; f0 < p9; f0 += 32) {
                int f = f0 + lane;
                bool act = (f < p9);
                int base = (f < p1) ? b0
                         : (f < p2) ? b1
                         : (f < p3) ? b2
                         : (f < p4) ? b3
                         : (f < p5) ? b4
                         : (f < p6) ? b5
                         : (f < p7) ? b6
                         : (f < p8) ? b7
                         : b8;
                bool hit = false;
                int jidx = 0;
                if (act) {
                    float4 p = g_bimg4[f + base];
                    float ddx = SUB(cx, p.x);
                    float ddy = SUB(cy, p.y);
                    float ddz = SUB(cz, p.z);
                    float r2 = ADD(ADD(MUL(ddx, ddx), MUL(ddy, ddy)), MUL(ddz, ddz));
                    float dd = __fsqrt_rn(r2);
                    hit = (dd < 5.0f) && (dd > 0.001f);
                    jidx = __float_as_int(p.w);
                }
                unsigned bal = __ballot_sync(0xffffffffu, hit);
                if (hit) {
                    int slot = cur + __popc(bal & ((1u << lane) - 1u));
                    if (slot < MAXPA) sjw[slot] = jidx;
                }
                cur += __popc(bal);
            }
        }
        __syncwarp();
        int k = min(cur, MAXPA);
        // rank sort by image idx (unique) -> exact reference order
        int vals[6], rnks[6];
        int nn = 0;
        for (int i2 = lane; i2 < k; i2 += 32) {
            int v = sjw[i2];
            int r = 0;
            for (int q = 0; q < k; q++) r += (sjw[q] < v);
            vals[nn] = v;
            rnks[nn] = r;
            nn++;
        }
        __syncwarp();
        for (int q = 0; q < nn; q++) sjw[rnks[q]] = vals[q];
        if (w < N && lane == 0) g_cnt[w] = k;
    }
    gbar(++gen);  // B2: counts complete

    // ================= PHASE C: offsets (redundant scan) + write =================
    {
        int cA[4];
        int myv = 0;
        int a0 = t * 4;
#pragma unroll
        for (int q = 0; q < 4; q++) {
            int a = a0 + q;
            cA[q] = (a < N) ? g_cnt[a] : 0;
            myv += cA[q];
        }
        int run = scanExcl1024(myv, stmp, lane, wid);
#pragma unroll
        for (int q = 0; q < 4; q++) {
            int a = a0 + q;
            if (a < N && (a & (NBLK - 1)) == b) sWoff[a >> 7] = run;
            run += cA[q];
        }
        __syncthreads();

        int w = wid * NBLK + b;
        if (w < N) {
            int off = sWoff[wid];
            int k = min(g_cnt[w], MAXPA);
            int* sjw = sj + wid * MAXPA;
            float fi = (float)w;
            for (int r = lane; r < k; r += 32) {
                int idx = sjw[r];
                int s = idx / N;
                int a = idx - s * N;
                int pos = off + r;
                out[pos] = fi;
                out[P + pos] = (float)a;
                out[2 * P + 3 * pos + 0] = sshifts[s * 3 + 0];
                out[2 * P + 3 * pos + 1] = sshifts[s * 3 + 1];
                out[2 * P + 3 * pos + 2] = sshifts[s * 3 + 2];
            }
        }
    }
}

// ---------------- launch ----------------
extern "C" void kernel_launch(void* const* d_in, const int* in_sizes, int n_in,
                              void* d_out, int out_size) {
    const int* period = (const int*)d_in[0];
    const float* coords = (const float*)d_in[1];
    const float* cell = (const float*)d_in[2];
    const float* mass = (const float*)d_in[3];
    float* out = (float*)d_out;

    int N = in_sizes[1] / 3;
    int P = out_size / 5;

    int smem = 32768 + 3 * 4 * N + (NCELL + 8) * 4 + 128;
    cudaFuncSetAttribute(k_all, cudaFuncAttributeMaxDynamicSharedMemorySize, smem);
    k_all<<<NBLK, NTHR, smem>>>(cell, period, coords, mass, N, P, out);
}